// round 9
// baseline (speedup 1.0000x reference)
#include <cuda_runtime.h>
#include <cstdint>

typedef unsigned long long ull;

#define L2E 1.4426950408889634f
#define LN2 0.6931471805599453f

// Inter-kernel scratch (static device memory: allowed)
__device__ float g_l128[(size_t)512 * 128 * 32];   // 8 MB
__device__ float g_l8 [(size_t)512 * 8 * 32];      // 512 KB

// ---------------------------------------------------------------------------
// Low-level helpers
// ---------------------------------------------------------------------------
__device__ __forceinline__ float ex2f(float x) {
    float r; asm("ex2.approx.f32 %0, %1;" : "=f"(r) : "f"(x)); return r;
}
__device__ __forceinline__ float lg2f(float x) {
    float r; asm("lg2.approx.f32 %0, %1;" : "=f"(r) : "f"(x)); return r;
}
__device__ __forceinline__ uint32_t s2u(const void* p) {
    return (uint32_t)__cvta_generic_to_shared(p);
}
__device__ __forceinline__ ull pack2(float x) {
    ull r; asm("mov.b64 %0, {%1, %1};" : "=l"(r) : "f"(x)); return r;
}
__device__ __forceinline__ void unpack2(ull v, float& lo, float& hi) {
    asm("mov.b64 {%0, %1}, %2;" : "=f"(lo), "=f"(hi) : "l"(v));
}
__device__ __forceinline__ ull fma2(ull a, ull b, ull c) {
    ull d; asm("fma.rn.f32x2 %0, %1, %2, %3;" : "=l"(d) : "l"(a), "l"(b), "l"(c)); return d;
}
__device__ __forceinline__ void lds2(ull& a, ull& b, uint32_t addr) {
    asm("ld.shared.v2.u64 {%0, %1}, [%2];" : "=l"(a), "=l"(b) : "r"(addr));
}
__device__ __forceinline__ void cp_async16(uint32_t dst, const void* src) {
    asm volatile("cp.async.cg.shared.global [%0], [%1], 16;" :: "r"(dst), "l"(src));
}
__device__ __forceinline__ void cp_commit() {
    asm volatile("cp.async.commit_group;");
}
template <int N>
__device__ __forceinline__ void cp_wait() {
    asm volatile("cp.async.wait_group %0;" :: "n"(N));
}

// m16n8k8 tf32 mma, D += A*B
__device__ __forceinline__ void mma_tf32(float c[4], const uint32_t a[4], const uint32_t b[2]) {
    asm("mma.sync.aligned.m16n8k8.row.col.f32.tf32.tf32.f32 "
        "{%0,%1,%2,%3}, {%4,%5,%6,%7}, {%8,%9}, {%0,%1,%2,%3};"
        : "+f"(c[0]), "+f"(c[1]), "+f"(c[2]), "+f"(c[3])
        : "r"(a[0]), "r"(a[1]), "r"(a[2]), "r"(a[3]), "r"(b[0]), "r"(b[1]));
}

#define WSLOT_FL (32 * 36)                 // weight slot: 1152 floats

// ---------------------------------------------------------------------------
// MMA node: warp computes one node for MT*16 batches (MT m16-tiles).
// Value slots: row-major [b*36 + k] (stride 36 -> conflict-free A-frag LDS).
// W slot: raw f32 bits, row-major [k*36 + j] (tf32 MMA truncates mantissa).
// ---------------------------------------------------------------------------
template <int MT, bool DUAL>
__device__ __forceinline__ void node_mma(const float* pa, const float* pb,
                                         const float* wp, float* po, int lane) {
    const int g = lane >> 2, tg = lane & 3;

    // ---- A fragments: a[mt][kt][r], r: 0=(u0,v0) 1=(u1,v0) 2=(u0,v1) 3=(u1,v1)
    float a[MT][4][4];
#pragma unroll
    for (int mt = 0; mt < MT; mt++)
#pragma unroll
        for (int kt = 0; kt < 4; kt++)
#pragma unroll
            for (int r = 0; r < 4; r++) {
                const int row = 16 * mt + 8 * (r & 1) + g;
                const int col = 8 * kt + 4 * (r >> 1) + tg;
                float v = pa[row * 36 + col];
                if (DUAL) v += pb[row * 36 + col];
                a[mt][kt][r] = v;
            }

    // ---- row max per (mt, u)
    float mx[MT][2];
#pragma unroll
    for (int mt = 0; mt < MT; mt++)
#pragma unroll
        for (int u = 0; u < 2; u++) {
            float m = fmaxf(a[mt][0][u], a[mt][0][u + 2]);
#pragma unroll
            for (int kt = 1; kt < 4; kt++)
                m = fmaxf(m, fmaxf(a[mt][kt][u], a[mt][kt][u + 2]));
            m = fmaxf(m, __shfl_xor_sync(0xffffffffu, m, 1));
            m = fmaxf(m, __shfl_xor_sync(0xffffffffu, m, 2));
            mx[mt][u] = m;
        }

    // ---- e = exp2((p - m) * L2E) as raw f32 bits (tf32 MMA truncates)
    uint32_t ua[MT][4][4];
#pragma unroll
    for (int mt = 0; mt < MT; mt++)
#pragma unroll
        for (int kt = 0; kt < 4; kt++)
#pragma unroll
            for (int r = 0; r < 4; r++) {
                const float nm = -mx[mt][r & 1] * L2E;
                ua[mt][kt][r] = __float_as_uint(ex2f(fmaf(a[mt][kt][r], L2E, nm)));
            }

    // ---- per-nt: load B frags, MT m-tiles of MMA, log + STS.64 stores
#pragma unroll
    for (int nt = 0; nt < 4; nt++) {
        uint32_t b[4][2];
#pragma unroll
        for (int kt = 0; kt < 4; kt++) {
            b[kt][0] = __float_as_uint(wp[(8 * kt + tg) * 36 + 8 * nt + g]);
            b[kt][1] = __float_as_uint(wp[(8 * kt + 4 + tg) * 36 + 8 * nt + g]);
        }
#pragma unroll
        for (int mt = 0; mt < MT; mt++) {
            float c[4] = {0.f, 0.f, 0.f, 0.f};
#pragma unroll
            for (int kt = 0; kt < 4; kt++)
                mma_tf32(c, ua[mt][kt], b[kt]);
#pragma unroll
            for (int u = 0; u < 2; u++) {
                const int row = 16 * mt + 8 * u + g;
                float2 o;
                o.x = fmaf(lg2f(c[2 * u]),     LN2, mx[mt][u]);
                o.y = fmaf(lg2f(c[2 * u + 1]), LN2, mx[mt][u]);
                *(float2*)(po + row * 36 + 8 * nt + 2 * tg) = o;
            }
        }
    }
}

// Async-stage NM weight matrices (raw f32) into stride-36 slots via cp.async.
template <int NM>
__device__ __forceinline__ void stage_w_async(uint32_t dst_s,
                                              const float* __restrict__ src,
                                              int tid) {
#pragma unroll
    for (int t = 0; t < NM * 2; t++) {
        const int c = tid + t * 128;
        const int m = c >> 8, rc = c & 255;       // chunk within matrix
        const int row = rc >> 3, col = rc & 7;    // 8 x 16B chunks per row
        cp_async16(dst_s + (uint32_t)(m * WSLOT_FL + row * 36 + col * 4) * 4u,
                   src + (size_t)m * 1024 + row * 32 + col * 4);
    }
}

// ---------------------------------------------------------------------------
// Tree kernel (MMA): 16-leaf subtree -> 1 node, MT*16 batches, 4 warps.
// Grid: (IN_F/16, 512/(MT*16)).
// smem: 8 value slots [MT*16 x 36] + 2x4 W slots (cp.async double-buffered).
// ---------------------------------------------------------------------------
template <int IN_F, int MT>
__global__ void __launch_bounds__(128, 2)
pc_tree_mma(const float* __restrict__ in, const float* __restrict__ W,
            float* __restrict__ outp) {
    constexpr int VSLOT_FL = MT * 16 * 36;
    constexpr int VAL_FL = 8 * VSLOT_FL;
    constexpr int NB = MT * 16;              // batches per block

    extern __shared__ float sm[];
    float* val = sm;
    float* wb0 = sm + VAL_FL;
    float* wb1 = wb0 + 4 * WSLOT_FL;

    const int s   = blockIdx.x;
    const int B0  = blockIdx.y * NB;
    const int tid = threadIdx.x;
    const int w = tid >> 5, lane = tid & 31;
    const uint32_t wb0s = s2u(wb0), wb1s = s2u(wb1);

    const int o0 = 2048 - IN_F;
    const int o1 = o0 + IN_F / 2, o2 = o1 + IN_F / 4, o3 = o2 + IN_F / 8;

    // ---- prologue: async-stage L0a -> wb0, L0b -> wb1; stage p-slots ----
    stage_w_async<4>(wb0s, W + (size_t)(o0 + s * 8) * 1024, tid);
    cp_commit();
    stage_w_async<4>(wb1s, W + (size_t)(o0 + s * 8 + 4) * 1024, tid);
    cp_commit();
    {
        const int k4 = lane & 7, bo = lane >> 3;
#pragma unroll
        for (int ns = 0; ns < 2; ns++) {
            const int n = 2 * w + ns;
            float* slot = val + n * VSLOT_FL;
            const float4* xA = (const float4*)(in + ((size_t)B0 * IN_F + (size_t)s * 16 + 2 * n) * 32);
            const float4* xB = xA + 8;   // sibling leaf, +32 floats
#pragma unroll
            for (int i = 0; i < MT * 4; i++) {
                const int bb = i * 4 + bo;
                const size_t roff = (size_t)bb * IN_F * 8;
                float4 va = xA[roff + k4];
                float4 vb = xB[roff + k4];
                float4 p{va.x + vb.x, va.y + vb.y, va.z + vb.z, va.w + vb.w};
                *(float4*)(slot + bb * 36 + 4 * k4) = p;
            }
        }
    }
    cp_wait<1>();               // L0a ready (L0b may still be in flight)
    __syncthreads();

    // R0: L0 nodes 0..3 (wb0), L0b arriving into wb1 meanwhile
    node_mma<MT, false>(val + w * VSLOT_FL, val + w * VSLOT_FL,
                        wb0 + w * WSLOT_FL, val + w * VSLOT_FL, lane);
    cp_wait<0>();
    __syncthreads();

    // R1: prefetch L1 -> wb0; compute L0 nodes 4..7 (wb1)
    stage_w_async<4>(wb0s, W + (size_t)(o1 + s * 4) * 1024, tid);
    cp_commit();
    node_mma<MT, false>(val + (4 + w) * VSLOT_FL, val + (4 + w) * VSLOT_FL,
                        wb1 + w * WSLOT_FL, val + (4 + w) * VSLOT_FL, lane);
    cp_wait<0>();
    __syncthreads();

    // R2: prefetch L2 -> wb1; compute L1 (wb0): slots 2w,2w+1 -> 2w
    stage_w_async<2>(wb1s, W + (size_t)(o2 + s * 2) * 1024, tid);
    cp_commit();
    node_mma<MT, true>(val + 2 * w * VSLOT_FL, val + (2 * w + 1) * VSLOT_FL,
                       wb0 + w * WSLOT_FL, val + 2 * w * VSLOT_FL, lane);
    cp_wait<0>();
    __syncthreads();

    // R3: prefetch L3 -> wb0; warps 0,1 compute L2 (wb1): 4w,4w+2 -> 4w
    stage_w_async<1>(wb0s, W + (size_t)(o3 + s) * 1024, tid);
    cp_commit();
    if (w < 2)
        node_mma<MT, true>(val + 4 * w * VSLOT_FL, val + (4 * w + 2) * VSLOT_FL,
                           wb1 + w * WSLOT_FL, val + 4 * w * VSLOT_FL, lane);
    cp_wait<0>();
    __syncthreads();

    // R4: L3 root (wb0): slots 0,4 -> slot 0
    if (w == 0)
        node_mma<MT, true>(val, val + 4 * VSLOT_FL, wb0, val, lane);
    __syncthreads();

    // ---- write root to global ----
    constexpr int OUT_F = IN_F / 16;
#pragma unroll
    for (int i = 0; i < MT; i++) {
        const int idx = tid + i * 128;
        const int bb = idx >> 3, k4 = idx & 7;
        float4 v = *(const float4*)(val + bb * 36 + 4 * k4);
        *(float4*)(outp + ((size_t)(B0 + bb) * OUT_F + s) * 32 + 4 * k4) = v;
    }
}

// ---------------------------------------------------------------------------
// FP32 scalar node path (tail kernel only)
// ---------------------------------------------------------------------------
__device__ __forceinline__ void node_core(float p[32], uint32_t waddr,
                                          float* po, int ostr) {
    float m0 = p[0], m1 = p[1], m2 = p[2], m3 = p[3];
#pragma unroll
    for (int k = 4; k < 32; k += 4) {
        m0 = fmaxf(m0, p[k]);     m1 = fmaxf(m1, p[k + 1]);
        m2 = fmaxf(m2, p[k + 2]); m3 = fmaxf(m3, p[k + 3]);
    }
    const float mx = fmaxf(fmaxf(m0, m1), fmaxf(m2, m3));
    const float nmx = -mx * L2E;
#pragma unroll
    for (int k = 0; k < 32; k++) p[k] = ex2f(fmaf(p[k], L2E, nmx));
    ull acc[16];
#pragma unroll
    for (int q = 0; q < 16; q++) acc[q] = 0ULL;
#pragma unroll 4
    for (int i = 0; i < 32; i++) {
        const ull ep = pack2(p[i]);
        const uint32_t ra = waddr + (uint32_t)i * 128u;
#pragma unroll
        for (int q = 0; q < 8; q++) {
            ull w0, w1; lds2(w0, w1, ra + (uint32_t)q * 16u);
            acc[2 * q]     = fma2(ep, w0, acc[2 * q]);
            acc[2 * q + 1] = fma2(ep, w1, acc[2 * q + 1]);
        }
    }
#pragma unroll
    for (int q = 0; q < 16; q++) {
        float y0, y1; unpack2(acc[q], y0, y1);
        po[(2 * q)     * ostr] = fmaf(lg2f(y0), LN2, mx);
        po[(2 * q + 1) * ostr] = fmaf(lg2f(y1), LN2, mx);
    }
}

__device__ __forceinline__ void node_g(const float* __restrict__ gp,
                                       uint32_t waddr, float* po, int ostr) {
    float p[32];
    const float4* g4 = (const float4*)gp;
#pragma unroll
    for (int q = 0; q < 8; q++) {
        float4 a = g4[q], bb = g4[q + 8];
        p[4 * q]     = a.x + bb.x; p[4 * q + 1] = a.y + bb.y;
        p[4 * q + 2] = a.z + bb.z; p[4 * q + 3] = a.w + bb.w;
    }
    node_core(p, waddr, po, ostr);
}

__device__ __forceinline__ void node_s(const float* sa, const float* sb, int istr,
                                       uint32_t waddr, float* po, int ostr) {
    float p[32];
#pragma unroll
    for (int k = 0; k < 32; k++) p[k] = sa[k * istr] + sb[k * istr];
    node_core(p, waddr, po, ostr);
}

// ---------------------------------------------------------------------------
// Tail: F=8 -> root + mixture (fp32). Grid 16 x 256 thr, 32 batches each.
// ---------------------------------------------------------------------------
#define SMEM_TAIL_FLOATS (8 * 1024 + 7 * 1024 + 32)

__global__ void __launch_bounds__(256, 2)
pc_tail8(const float* __restrict__ in, const float* __restrict__ W,
         const float* __restrict__ mlw, float* __restrict__ outp) {
    extern __shared__ float sm[];
    float* val = sm;
    float* wb  = sm + 8192;
    float* lw  = sm + 8192 + 7168;

    const int B0  = blockIdx.x * 32;
    const int tid = threadIdx.x;
    const int w = tid >> 5, lane = tid & 31;

    {
        const float4* src = (const float4*)(W + (size_t)2040 * 1024);
        float4* dst = (float4*)wb;
#pragma unroll
        for (int i = 0; i < 7; i++) dst[tid + i * 256] = src[tid + i * 256];
    }
    if (tid < 32) lw[tid] = mlw[tid];
    __syncthreads();

    if (w < 4) {
        const float* gp = in + ((size_t)(B0 + lane) * 8 + 2 * w) * 32;
        node_g(gp, s2u(wb + w * 1024), val + w * 1024 + lane, 32);
    }
    __syncthreads();

    if (w < 2)
        node_s(val + (2 * w) * 1024 + lane, val + (2 * w + 1) * 1024 + lane, 32,
               s2u(wb + (4 + w) * 1024), val + (2 * w) * 1024 + lane, 32);
    __syncthreads();

    if (w == 0)
        node_s(val + lane, val + 2 * 1024 + lane, 32,
               s2u(wb + 6 * 1024), val + lane, 32);
    __syncthreads();

    if (tid < 32) {
        const int b2 = tid;
        float m1 = lw[0];
        for (int k = 1; k < 32; k++) m1 = fmaxf(m1, lw[k]);
        float s1 = 0.f;
        for (int k = 0; k < 32; k++) s1 += ex2f((lw[k] - m1) * L2E);
        const float lse = fmaf(lg2f(s1), LN2, m1);

        float m2 = -1e30f;
        for (int k = 0; k < 32; k++)
            m2 = fmaxf(m2, 2.f * val[k * 32 + b2] + lw[k] - lse);
        float s2 = 0.f;
        for (int k = 0; k < 32; k++)
            s2 += ex2f((2.f * val[k * 32 + b2] + lw[k] - lse - m2) * L2E);
        outp[B0 + b2] = fmaf(lg2f(s2), LN2, m2);
    }
}

// ---------------------------------------------------------------------------
// Launch. Inputs: x f32[512,2048,32], weights f32[2047,32,32],
// fold_idx i32 (trivial (2f,2f+1) pairing -> computed), mix_logw f32[32].
// Output: f32[512].
// ---------------------------------------------------------------------------
extern "C" void kernel_launch(void* const* d_in, const int* in_sizes, int n_in,
                              void* d_out, int out_size) {
    const float* x   = (const float*)d_in[0];
    const float* W   = (const float*)d_in[1];
    const float* mlw = (const float*)d_in[3];
    float* out = (float*)d_out;

    float* g1; cudaGetSymbolAddress((void**)&g1, g_l128);
    float* g2; cudaGetSymbolAddress((void**)&g2, g_l8);

    const int smem_k1 = (8 * 64 * 36 + 8 * WSLOT_FL) * sizeof(float);   // 110592 B
    const int smem_k2 = (8 * 32 * 36 + 8 * WSLOT_FL) * sizeof(float);   // 73728 B
    const int smem_tail = SMEM_TAIL_FLOATS * sizeof(float);
    cudaFuncSetAttribute((const void*)pc_tree_mma<2048, 4>,
                         cudaFuncAttributeMaxDynamicSharedMemorySize, smem_k1);
    cudaFuncSetAttribute((const void*)pc_tree_mma<128, 2>,
                         cudaFuncAttributeMaxDynamicSharedMemorySize, smem_k2);
    cudaFuncSetAttribute((const void*)pc_tail8,
                         cudaFuncAttributeMaxDynamicSharedMemorySize, smem_tail);

    pc_tree_mma<2048, 4><<<dim3(128, 8), 128, smem_k1>>>(x,  W, g1);
    pc_tree_mma<128, 2><<<dim3(8, 16),  128, smem_k2>>>(g1, W, g2);
    pc_tail8           <<<16,           256, smem_tail>>>(g2, W, mlw, out);
}

// round 10
// speedup vs baseline: 1.4142x; 1.4142x over previous
#include <cuda_runtime.h>
#include <cstdint>

typedef unsigned long long ull;

#define L2E 1.4426950408889634f
#define LN2 0.6931471805599453f

// Inter-kernel scratch (static device memory: allowed)
__device__ float g_l128[(size_t)512 * 128 * 32];   // 8 MB
__device__ float g_l8 [(size_t)512 * 8 * 32];      // 512 KB

// ---------------------------------------------------------------------------
// Low-level helpers
// ---------------------------------------------------------------------------
__device__ __forceinline__ float ex2f(float x) {
    float r; asm("ex2.approx.f32 %0, %1;" : "=f"(r) : "f"(x)); return r;
}
__device__ __forceinline__ float lg2f(float x) {
    float r; asm("lg2.approx.f32 %0, %1;" : "=f"(r) : "f"(x)); return r;
}
__device__ __forceinline__ uint32_t s2u(const void* p) {
    return (uint32_t)__cvta_generic_to_shared(p);
}
__device__ __forceinline__ ull pack2(float x) {
    ull r; asm("mov.b64 %0, {%1, %1};" : "=l"(r) : "f"(x)); return r;
}
__device__ __forceinline__ void unpack2(ull v, float& lo, float& hi) {
    asm("mov.b64 {%0, %1}, %2;" : "=f"(lo), "=f"(hi) : "l"(v));
}
__device__ __forceinline__ ull fma2(ull a, ull b, ull c) {
    ull d; asm("fma.rn.f32x2 %0, %1, %2, %3;" : "=l"(d) : "l"(a), "l"(b), "l"(c)); return d;
}
__device__ __forceinline__ void lds2(ull& a, ull& b, uint32_t addr) {
    asm("ld.shared.v2.u64 {%0, %1}, [%2];" : "=l"(a), "=l"(b) : "r"(addr));
}

// m16n8k8 tf32 mma, D += A*B
__device__ __forceinline__ void mma_tf32(float c[4], const uint32_t a[4], const uint32_t b[2]) {
    asm("mma.sync.aligned.m16n8k8.row.col.f32.tf32.tf32.f32 "
        "{%0,%1,%2,%3}, {%4,%5,%6,%7}, {%8,%9}, {%0,%1,%2,%3};"
        : "+f"(c[0]), "+f"(c[1]), "+f"(c[2]), "+f"(c[3])
        : "r"(a[0]), "r"(a[1]), "r"(a[2]), "r"(a[3]), "r"(b[0]), "r"(b[1]));
}

// ---------------------------------------------------------------------------
// MMA node: warp computes one node for MT*16 batches (MT m16-tiles).
// Value slots (smem): row-major [b*36 + k] (stride 36 -> conflict-free LDS).
// W: GLOBAL row-major 32x32 (L1/L2-resident; tf32 MMA truncates mantissa).
// ---------------------------------------------------------------------------
template <int MT, bool DUAL>
__device__ __forceinline__ void node_mma(const float* pa, const float* pb,
                                         const float* __restrict__ wp,
                                         float* po, int lane) {
    const int g = lane >> 2, tg = lane & 3;

    // ---- A fragments: a[mt][kt][r], r: 0=(u0,v0) 1=(u1,v0) 2=(u0,v1) 3=(u1,v1)
    float a[MT][4][4];
#pragma unroll
    for (int mt = 0; mt < MT; mt++)
#pragma unroll
        for (int kt = 0; kt < 4; kt++)
#pragma unroll
            for (int r = 0; r < 4; r++) {
                const int row = 16 * mt + 8 * (r & 1) + g;
                const int col = 8 * kt + 4 * (r >> 1) + tg;
                float v = pa[row * 36 + col];
                if (DUAL) v += pb[row * 36 + col];
                a[mt][kt][r] = v;
            }

    // ---- row max per (mt, u)
    float mx[MT][2];
#pragma unroll
    for (int mt = 0; mt < MT; mt++)
#pragma unroll
        for (int u = 0; u < 2; u++) {
            float m = fmaxf(a[mt][0][u], a[mt][0][u + 2]);
#pragma unroll
            for (int kt = 1; kt < 4; kt++)
                m = fmaxf(m, fmaxf(a[mt][kt][u], a[mt][kt][u + 2]));
            m = fmaxf(m, __shfl_xor_sync(0xffffffffu, m, 1));
            m = fmaxf(m, __shfl_xor_sync(0xffffffffu, m, 2));
            mx[mt][u] = m;
        }

    // ---- e = exp2((p - m) * L2E) as raw f32 bits (tf32 MMA truncates)
    uint32_t ua[MT][4][4];
#pragma unroll
    for (int mt = 0; mt < MT; mt++)
#pragma unroll
        for (int kt = 0; kt < 4; kt++)
#pragma unroll
            for (int r = 0; r < 4; r++) {
                const float nm = -mx[mt][r & 1] * L2E;
                ua[mt][kt][r] = __float_as_uint(ex2f(fmaf(a[mt][kt][r], L2E, nm)));
            }

    // ---- per-nt: B frags from GLOBAL (L1/L2 hit), MT m-tiles MMA, log, STS.64
#pragma unroll
    for (int nt = 0; nt < 4; nt++) {
        uint32_t b[4][2];
#pragma unroll
        for (int kt = 0; kt < 4; kt++) {
            b[kt][0] = __float_as_uint(wp[(8 * kt + tg) * 32 + 8 * nt + g]);
            b[kt][1] = __float_as_uint(wp[(8 * kt + 4 + tg) * 32 + 8 * nt + g]);
        }
#pragma unroll
        for (int mt = 0; mt < MT; mt++) {
            float c[4] = {0.f, 0.f, 0.f, 0.f};
#pragma unroll
            for (int kt = 0; kt < 4; kt++)
                mma_tf32(c, ua[mt][kt], b[kt]);
#pragma unroll
            for (int u = 0; u < 2; u++) {
                const int row = 16 * mt + 8 * u + g;
                float2 o;
                o.x = fmaf(lg2f(c[2 * u]),     LN2, mx[mt][u]);
                o.y = fmaf(lg2f(c[2 * u + 1]), LN2, mx[mt][u]);
                *(float2*)(po + row * 36 + 8 * nt + 2 * tg) = o;
            }
        }
    }
}

// ---------------------------------------------------------------------------
// Tree kernel (MMA): 16-leaf subtree -> 1 node, MT*16 batches, 4 warps.
// Grid: (IN_F/16, 512/(MT*16)). smem: 8 value slots only (36.9 KB at MT=2)
// -> 4 blocks/SM. W read directly from global (L1/L2-cached).
// ---------------------------------------------------------------------------
template <int IN_F, int MT>
__global__ void __launch_bounds__(128, 4)
pc_tree_mma(const float* __restrict__ in, const float* __restrict__ W,
            float* __restrict__ outp) {
    constexpr int VSLOT_FL = MT * 16 * 36;
    constexpr int VAL_FL = 8 * VSLOT_FL;
    constexpr int NB = MT * 16;              // batches per block

    extern __shared__ float sm[];
    float* val = sm;

    const int s   = blockIdx.x;
    const int B0  = blockIdx.y * NB;
    const int tid = threadIdx.x;
    const int w = tid >> 5, lane = tid & 31;

    const int o0 = 2048 - IN_F;
    const int o1 = o0 + IN_F / 2, o2 = o1 + IN_F / 4, o3 = o2 + IN_F / 8;

    // ---- prologue: stage p-slots (leaf-pair sums), coalesced ----
    {
        const int k4 = lane & 7, bo = lane >> 3;
#pragma unroll
        for (int ns = 0; ns < 2; ns++) {
            const int n = 2 * w + ns;
            float* slot = val + n * VSLOT_FL;
            const float4* xA = (const float4*)(in + ((size_t)B0 * IN_F + (size_t)s * 16 + 2 * n) * 32);
            const float4* xB = xA + 8;   // sibling leaf, +32 floats
#pragma unroll
            for (int i = 0; i < MT * 4; i++) {
                const int bb = i * 4 + bo;
                const size_t roff = (size_t)bb * IN_F * 8;
                float4 va = xA[roff + k4];
                float4 vb = xB[roff + k4];
                float4 p{va.x + vb.x, va.y + vb.y, va.z + vb.z, va.w + vb.w};
                *(float4*)(slot + bb * 36 + 4 * k4) = p;
            }
        }
    }
    __syncthreads();

    // R0: L0 nodes 0..3 (in place)
    node_mma<MT, false>(val + w * VSLOT_FL, val + w * VSLOT_FL,
                        W + (size_t)(o0 + s * 8 + w) * 1024,
                        val + w * VSLOT_FL, lane);
    __syncthreads();

    // R1: L0 nodes 4..7
    node_mma<MT, false>(val + (4 + w) * VSLOT_FL, val + (4 + w) * VSLOT_FL,
                        W + (size_t)(o0 + s * 8 + 4 + w) * 1024,
                        val + (4 + w) * VSLOT_FL, lane);
    __syncthreads();

    // R2: L1, node j=w: slots 2w,2w+1 -> 2w
    node_mma<MT, true>(val + 2 * w * VSLOT_FL, val + (2 * w + 1) * VSLOT_FL,
                       W + (size_t)(o1 + s * 4 + w) * 1024,
                       val + 2 * w * VSLOT_FL, lane);
    __syncthreads();

    // R3: L2, warps 0,1: slots 4w,4w+2 -> 4w
    if (w < 2)
        node_mma<MT, true>(val + 4 * w * VSLOT_FL, val + (4 * w + 2) * VSLOT_FL,
                           W + (size_t)(o2 + s * 2 + w) * 1024,
                           val + 4 * w * VSLOT_FL, lane);
    __syncthreads();

    // R4: L3 root: slots 0,4 -> slot 0
    if (w == 0)
        node_mma<MT, true>(val, val + 4 * VSLOT_FL,
                           W + (size_t)(o3 + s) * 1024, val, lane);
    __syncthreads();

    // ---- write root to global ----
    constexpr int OUT_F = IN_F / 16;
#pragma unroll
    for (int i = 0; i < MT; i++) {
        const int idx = tid + i * 128;
        const int bb = idx >> 3, k4 = idx & 7;
        float4 v = *(const float4*)(val + bb * 36 + 4 * k4);
        *(float4*)(outp + ((size_t)(B0 + bb) * OUT_F + s) * 32 + 4 * k4) = v;
    }
}

// ---------------------------------------------------------------------------
// FP32 scalar node path (tail kernel only)
// ---------------------------------------------------------------------------
__device__ __forceinline__ void node_core(float p[32], uint32_t waddr,
                                          float* po, int ostr) {
    float m0 = p[0], m1 = p[1], m2 = p[2], m3 = p[3];
#pragma unroll
    for (int k = 4; k < 32; k += 4) {
        m0 = fmaxf(m0, p[k]);     m1 = fmaxf(m1, p[k + 1]);
        m2 = fmaxf(m2, p[k + 2]); m3 = fmaxf(m3, p[k + 3]);
    }
    const float mx = fmaxf(fmaxf(m0, m1), fmaxf(m2, m3));
    const float nmx = -mx * L2E;
#pragma unroll
    for (int k = 0; k < 32; k++) p[k] = ex2f(fmaf(p[k], L2E, nmx));
    ull acc[16];
#pragma unroll
    for (int q = 0; q < 16; q++) acc[q] = 0ULL;
#pragma unroll 4
    for (int i = 0; i < 32; i++) {
        const ull ep = pack2(p[i]);
        const uint32_t ra = waddr + (uint32_t)i * 128u;
#pragma unroll
        for (int q = 0; q < 8; q++) {
            ull w0, w1; lds2(w0, w1, ra + (uint32_t)q * 16u);
            acc[2 * q]     = fma2(ep, w0, acc[2 * q]);
            acc[2 * q + 1] = fma2(ep, w1, acc[2 * q + 1]);
        }
    }
#pragma unroll
    for (int q = 0; q < 16; q++) {
        float y0, y1; unpack2(acc[q], y0, y1);
        po[(2 * q)     * ostr] = fmaf(lg2f(y0), LN2, mx);
        po[(2 * q + 1) * ostr] = fmaf(lg2f(y1), LN2, mx);
    }
}

__device__ __forceinline__ void node_g(const float* __restrict__ gp,
                                       uint32_t waddr, float* po, int ostr) {
    float p[32];
    const float4* g4 = (const float4*)gp;
#pragma unroll
    for (int q = 0; q < 8; q++) {
        float4 a = g4[q], bb = g4[q + 8];
        p[4 * q]     = a.x + bb.x; p[4 * q + 1] = a.y + bb.y;
        p[4 * q + 2] = a.z + bb.z; p[4 * q + 3] = a.w + bb.w;
    }
    node_core(p, waddr, po, ostr);
}

__device__ __forceinline__ void node_s(const float* sa, const float* sb, int istr,
                                       uint32_t waddr, float* po, int ostr) {
    float p[32];
#pragma unroll
    for (int k = 0; k < 32; k++) p[k] = sa[k * istr] + sb[k * istr];
    node_core(p, waddr, po, ostr);
}

// ---------------------------------------------------------------------------
// Tail: F=8 -> root + mixture (fp32). Grid 16 x 256 thr, 32 batches each.
// ---------------------------------------------------------------------------
#define SMEM_TAIL_FLOATS (8 * 1024 + 7 * 1024 + 32)

__global__ void __launch_bounds__(256, 2)
pc_tail8(const float* __restrict__ in, const float* __restrict__ W,
         const float* __restrict__ mlw, float* __restrict__ outp) {
    extern __shared__ float sm[];
    float* val = sm;
    float* wb  = sm + 8192;
    float* lw  = sm + 8192 + 7168;

    const int B0  = blockIdx.x * 32;
    const int tid = threadIdx.x;
    const int w = tid >> 5, lane = tid & 31;

    {
        const float4* src = (const float4*)(W + (size_t)2040 * 1024);
        float4* dst = (float4*)wb;
#pragma unroll
        for (int i = 0; i < 7; i++) dst[tid + i * 256] = src[tid + i * 256];
    }
    if (tid < 32) lw[tid] = mlw[tid];
    __syncthreads();

    if (w < 4) {
        const float* gp = in + ((size_t)(B0 + lane) * 8 + 2 * w) * 32;
        node_g(gp, s2u(wb + w * 1024), val + w * 1024 + lane, 32);
    }
    __syncthreads();

    if (w < 2)
        node_s(val + (2 * w) * 1024 + lane, val + (2 * w + 1) * 1024 + lane, 32,
               s2u(wb + (4 + w) * 1024), val + (2 * w) * 1024 + lane, 32);
    __syncthreads();

    if (w == 0)
        node_s(val + lane, val + 2 * 1024 + lane, 32,
               s2u(wb + 6 * 1024), val + lane, 32);
    __syncthreads();

    if (tid < 32) {
        const int b2 = tid;
        float m1 = lw[0];
        for (int k = 1; k < 32; k++) m1 = fmaxf(m1, lw[k]);
        float s1 = 0.f;
        for (int k = 0; k < 32; k++) s1 += ex2f((lw[k] - m1) * L2E);
        const float lse = fmaf(lg2f(s1), LN2, m1);

        float m2 = -1e30f;
        for (int k = 0; k < 32; k++)
            m2 = fmaxf(m2, 2.f * val[k * 32 + b2] + lw[k] - lse);
        float s2 = 0.f;
        for (int k = 0; k < 32; k++)
            s2 += ex2f((2.f * val[k * 32 + b2] + lw[k] - lse - m2) * L2E);
        outp[B0 + b2] = fmaf(lg2f(s2), LN2, m2);
    }
}

// ---------------------------------------------------------------------------
// Launch. Inputs: x f32[512,2048,32], weights f32[2047,32,32],
// fold_idx i32 (trivial (2f,2f+1) pairing -> computed), mix_logw f32[32].
// Output: f32[512].
// ---------------------------------------------------------------------------
extern "C" void kernel_launch(void* const* d_in, const int* in_sizes, int n_in,
                              void* d_out, int out_size) {
    const float* x   = (const float*)d_in[0];
    const float* W   = (const float*)d_in[1];
    const float* mlw = (const float*)d_in[3];
    float* out = (float*)d_out;

    float* g1; cudaGetSymbolAddress((void**)&g1, g_l128);
    float* g2; cudaGetSymbolAddress((void**)&g2, g_l8);

    const int smem_k = (8 * 32 * 36) * sizeof(float);       // 36864 B
    const int smem_tail = SMEM_TAIL_FLOATS * sizeof(float);
    cudaFuncSetAttribute((const void*)pc_tree_mma<2048, 2>,
                         cudaFuncAttributeMaxDynamicSharedMemorySize, smem_k);
    cudaFuncSetAttribute((const void*)pc_tree_mma<128, 2>,
                         cudaFuncAttributeMaxDynamicSharedMemorySize, smem_k);
    cudaFuncSetAttribute((const void*)pc_tail8,
                         cudaFuncAttributeMaxDynamicSharedMemorySize, smem_tail);

    pc_tree_mma<2048, 2><<<dim3(128, 16), 128, smem_k>>>(x,  W, g1);
    pc_tree_mma<128, 2><<<dim3(8, 16),   128, smem_k>>>(g1, W, g2);
    pc_tail8            <<<16,           256, smem_tail>>>(g2, W, mlw, out);
}

// round 11
// speedup vs baseline: 1.5473x; 1.0941x over previous
#include <cuda_runtime.h>
#include <cstdint>

#define L2E 1.4426950408889634f
#define LN2 0.6931471805599453f

// Inter-kernel (Y, m) scratch (static device memory: allowed)
__device__ float g_Y1[(size_t)512 * 128 * 32];   // 8 MB
__device__ float g_m1[(size_t)512 * 128];
__device__ float g_Y2[(size_t)512 * 8 * 32];
__device__ float g_m2[(size_t)512 * 8];

// ---------------------------------------------------------------------------
__device__ __forceinline__ float ex2f(float x) {
    float r; asm("ex2.approx.f32 %0, %1;" : "=f"(r) : "f"(x)); return r;
}
__device__ __forceinline__ float lg2f(float x) {
    float r; asm("lg2.approx.f32 %0, %1;" : "=f"(r) : "f"(x)); return r;
}
__device__ __forceinline__ float rcpf(float x) {
    float r; asm("rcp.approx.f32 %0, %1;" : "=f"(r) : "f"(x)); return r;
}
// m16n8k8 tf32 mma, D += A*B (A passed as f32, truncated by HW)
__device__ __forceinline__ void mma_tf32(float c[4], const float a[4], const uint32_t b[2]) {
    asm("mma.sync.aligned.m16n8k8.row.col.f32.tf32.tf32.f32 "
        "{%0,%1,%2,%3}, {%4,%5,%6,%7}, {%8,%9}, {%0,%1,%2,%3};"
        : "+f"(c[0]), "+f"(c[1]), "+f"(c[2]), "+f"(c[3])
        : "r"(__float_as_uint(a[0])), "r"(__float_as_uint(a[1])),
          "r"(__float_as_uint(a[2])), "r"(__float_as_uint(a[3])),
          "r"(b[0]), "r"(b[1]));
}

// Value slots (smem): row-major [b*36 + k], stride 36 -> conflict-free LDS.
// W read directly from GLOBAL row-major 32x32 (L1/L2-resident).

// ---------------------------------------------------------------------------
// Leaf node (log-domain input p in slot): e=exp2((p-m)*L2E), Y'=e@W, m'=max.
// ---------------------------------------------------------------------------
template <int MT>
__device__ __forceinline__ void node_leaf(const float* pa, const float* __restrict__ wp,
                                          float* po, float* mo, int lane) {
    const int g = lane >> 2, tg = lane & 3;
    float a[MT][4][4];
#pragma unroll
    for (int mt = 0; mt < MT; mt++)
#pragma unroll
        for (int kt = 0; kt < 4; kt++)
#pragma unroll
            for (int r = 0; r < 4; r++)
                a[mt][kt][r] = pa[(16*mt + 8*(r&1) + g) * 36 + 8*kt + 4*(r>>1) + tg];

    float mx[MT][2];
#pragma unroll
    for (int mt = 0; mt < MT; mt++)
#pragma unroll
        for (int u = 0; u < 2; u++) {
            float m = fmaxf(a[mt][0][u], a[mt][0][u+2]);
#pragma unroll
            for (int kt = 1; kt < 4; kt++)
                m = fmaxf(m, fmaxf(a[mt][kt][u], a[mt][kt][u+2]));
            m = fmaxf(m, __shfl_xor_sync(0xffffffffu, m, 1));
            m = fmaxf(m, __shfl_xor_sync(0xffffffffu, m, 2));
            mx[mt][u] = m;
        }
#pragma unroll
    for (int mt = 0; mt < MT; mt++)
#pragma unroll
        for (int kt = 0; kt < 4; kt++)
#pragma unroll
            for (int r = 0; r < 4; r++)
                a[mt][kt][r] = ex2f(fmaf(a[mt][kt][r], L2E, -mx[mt][r&1] * L2E));

#pragma unroll
    for (int nt = 0; nt < 4; nt++) {
        uint32_t b[4][2];
#pragma unroll
        for (int kt = 0; kt < 4; kt++) {
            b[kt][0] = __float_as_uint(wp[(8*kt + tg) * 32 + 8*nt + g]);
            b[kt][1] = __float_as_uint(wp[(8*kt + 4 + tg) * 32 + 8*nt + g]);
        }
#pragma unroll
        for (int mt = 0; mt < MT; mt++) {
            float c[4] = {0.f, 0.f, 0.f, 0.f};
#pragma unroll
            for (int kt = 0; kt < 4; kt++) mma_tf32(c, a[mt][kt], b[kt]);
#pragma unroll
            for (int u = 0; u < 2; u++)
                *(float2*)(po + (16*mt + 8*u + g) * 36 + 8*nt + 2*tg) =
                    make_float2(c[2*u], c[2*u+1]);
        }
    }
#pragma unroll
    for (int mt = 0; mt < MT; mt++)
#pragma unroll
        for (int u = 0; u < 2; u++)
            if (tg == 0) mo[16*mt + 8*u + g] = mx[mt][u];
}

// ---------------------------------------------------------------------------
// Linear node: e = (Yl*Yr)/max, Y'=e@W, m' = ml+mr+ln(max).
// PRE: slot already holds the product and mbuf the summed m.
// ---------------------------------------------------------------------------
template <int MT, bool PRE>
__device__ __forceinline__ void node_lin(const float* pa, const float* pb,
                                         const float* ma, const float* mb,
                                         const float* __restrict__ wp,
                                         float* po, float* mo, int lane) {
    const int g = lane >> 2, tg = lane & 3;
    float a[MT][4][4];
#pragma unroll
    for (int mt = 0; mt < MT; mt++)
#pragma unroll
        for (int kt = 0; kt < 4; kt++)
#pragma unroll
            for (int r = 0; r < 4; r++) {
                const int off = (16*mt + 8*(r&1) + g) * 36 + 8*kt + 4*(r>>1) + tg;
                float v = pa[off];
                if constexpr (!PRE) v *= pb[off];
                a[mt][kt][r] = v;
            }
    float ms[MT][2];
#pragma unroll
    for (int mt = 0; mt < MT; mt++)
#pragma unroll
        for (int u = 0; u < 2; u++) {
            const int row = 16*mt + 8*u + g;
            float mm = ma[row];
            if constexpr (!PRE) mm += mb[row];
            ms[mt][u] = mm;
        }
    float Mx[MT][2], rv[MT][2];
#pragma unroll
    for (int mt = 0; mt < MT; mt++)
#pragma unroll
        for (int u = 0; u < 2; u++) {
            float m = fmaxf(a[mt][0][u], a[mt][0][u+2]);
#pragma unroll
            for (int kt = 1; kt < 4; kt++)
                m = fmaxf(m, fmaxf(a[mt][kt][u], a[mt][kt][u+2]));
            m = fmaxf(m, __shfl_xor_sync(0xffffffffu, m, 1));
            m = fmaxf(m, __shfl_xor_sync(0xffffffffu, m, 2));
            Mx[mt][u] = m;
            rv[mt][u] = rcpf(m);
        }
#pragma unroll
    for (int mt = 0; mt < MT; mt++)
#pragma unroll
        for (int kt = 0; kt < 4; kt++)
#pragma unroll
            for (int r = 0; r < 4; r++)
                a[mt][kt][r] *= rv[mt][r&1];

#pragma unroll
    for (int nt = 0; nt < 4; nt++) {
        uint32_t b[4][2];
#pragma unroll
        for (int kt = 0; kt < 4; kt++) {
            b[kt][0] = __float_as_uint(wp[(8*kt + tg) * 32 + 8*nt + g]);
            b[kt][1] = __float_as_uint(wp[(8*kt + 4 + tg) * 32 + 8*nt + g]);
        }
#pragma unroll
        for (int mt = 0; mt < MT; mt++) {
            float c[4] = {0.f, 0.f, 0.f, 0.f};
#pragma unroll
            for (int kt = 0; kt < 4; kt++) mma_tf32(c, a[mt][kt], b[kt]);
#pragma unroll
            for (int u = 0; u < 2; u++)
                *(float2*)(po + (16*mt + 8*u + g) * 36 + 8*nt + 2*tg) =
                    make_float2(c[2*u], c[2*u+1]);
        }
    }
#pragma unroll
    for (int mt = 0; mt < MT; mt++)
#pragma unroll
        for (int u = 0; u < 2; u++)
            if (tg == 0)
                mo[16*mt + 8*u + g] = fmaf(lg2f(Mx[mt][u]), LN2, ms[mt][u]);
}

// ---------------------------------------------------------------------------
// Stage sibling pairs into slots: slot n = child(2n) (+ or *) child(2n+1).
// NS slots per warp. Coalesced float4 loads, stride-36 padded stores.
// ---------------------------------------------------------------------------
template <int IN_F, int MT, int NS, bool MULT>
__device__ __forceinline__ void stage_pairs(const float* __restrict__ src,
                                            float* val, int w, int lane) {
    constexpr int VS = MT * 16 * 36;
    const int k4 = lane & 7, bo = lane >> 3;
#pragma unroll
    for (int ns = 0; ns < NS; ns++) {
        const int n = NS * w + ns;
        float* slot = val + n * VS;
        const float4* xA = (const float4*)(src + (size_t)(2 * n) * 32);
        const float4* xB = xA + 8;
#pragma unroll
        for (int i = 0; i < MT * 4; i++) {
            const int bb = i * 4 + bo;
            const size_t roff = (size_t)bb * IN_F * 8;
            float4 va = xA[roff + k4], vb = xB[roff + k4];
            float4 p;
            if (MULT) p = make_float4(va.x*vb.x, va.y*vb.y, va.z*vb.z, va.w*vb.w);
            else      p = make_float4(va.x+vb.x, va.y+vb.y, va.z+vb.z, va.w+vb.w);
            *(float4*)(slot + bb * 36 + 4 * k4) = p;
        }
    }
}

// ---------------------------------------------------------------------------
// K1: x (log) -> 16-leaf subtree root (Y, m). Grid (IN_F/16, 512/NB), 4 warps.
// ---------------------------------------------------------------------------
template <int IN_F, int MT>
__global__ void __launch_bounds__(128, 4)
pc_k1(const float* __restrict__ in, const float* __restrict__ W,
      float* __restrict__ outY, float* __restrict__ outM) {
    constexpr int VS = MT * 16 * 36, NB = MT * 16, OUT_F = IN_F / 16;
    extern __shared__ float sm[];
    float* val  = sm;
    float* mbuf = sm + 8 * VS;
    const int s = blockIdx.x, B0 = blockIdx.y * NB;
    const int tid = threadIdx.x, w = tid >> 5, lane = tid & 31;
    const int o0 = 2048 - IN_F, o1 = o0 + IN_F/2, o2 = o1 + IN_F/4, o3 = o2 + IN_F/8;

    stage_pairs<IN_F, MT, 2, false>(in + ((size_t)B0 * IN_F + s * 16) * 32, val, w, lane);
    __syncthreads();

    // L0 (log->linear), two nodes per warp, in place, no barrier between
    node_leaf<MT>(val + w*VS, W + (size_t)(o0 + s*8 + w)*1024,
                  val + w*VS, mbuf + w*NB, lane);
    node_leaf<MT>(val + (4+w)*VS, W + (size_t)(o0 + s*8 + 4 + w)*1024,
                  val + (4+w)*VS, mbuf + (4+w)*NB, lane);
    __syncthreads();

    node_lin<MT, false>(val + 2*w*VS, val + (2*w+1)*VS, mbuf + 2*w*NB, mbuf + (2*w+1)*NB,
                        W + (size_t)(o1 + s*4 + w)*1024, val + 2*w*VS, mbuf + 2*w*NB, lane);
    __syncthreads();

    if (w < 2)
        node_lin<MT, false>(val + 4*w*VS, val + (4*w+2)*VS, mbuf + 4*w*NB, mbuf + (4*w+2)*NB,
                            W + (size_t)(o2 + s*2 + w)*1024, val + 4*w*VS, mbuf + 4*w*NB, lane);
    __syncthreads();

    if (w == 0)
        node_lin<MT, false>(val, val + 4*VS, mbuf, mbuf + 4*NB,
                            W + (size_t)(o3 + s)*1024, val, mbuf, lane);
    __syncthreads();

#pragma unroll
    for (int i = 0; i < MT; i++) {
        const int idx = tid + i * 128;
        const int bb = idx >> 3, k4 = idx & 7;
        float4 v = *(const float4*)(val + bb * 36 + 4 * k4);
        *(float4*)(outY + ((size_t)(B0 + bb) * OUT_F + s) * 32 + 4 * k4) = v;
    }
    if (tid < NB) outM[(size_t)(B0 + tid) * OUT_F + s] = mbuf[tid];
}

// ---------------------------------------------------------------------------
// K2: (Y,m)[128] -> (Y,m)[8]. All-linear. Grid (8, 512/NB).
// ---------------------------------------------------------------------------
template <int MT>
__global__ void __launch_bounds__(128, 4)
pc_k2(const float* __restrict__ inY, const float* __restrict__ inM,
      const float* __restrict__ W,
      float* __restrict__ outY, float* __restrict__ outM) {
    constexpr int IN_F = 128, VS = MT * 16 * 36, NB = MT * 16, OUT_F = 8;
    extern __shared__ float sm[];
    float* val  = sm;
    float* mbuf = sm + 8 * VS;
    const int s = blockIdx.x, B0 = blockIdx.y * NB;
    const int tid = threadIdx.x, w = tid >> 5, lane = tid & 31;
    const int o0 = 1920, o1 = 1984, o2 = 2016, o3 = 2032;

    stage_pairs<IN_F, MT, 2, true>(inY + ((size_t)B0 * IN_F + s * 16) * 32, val, w, lane);
#pragma unroll
    for (int t = 0; t < (8 * NB) / 128; t++) {
        const int idx = tid + t * 128;
        const int n = idx / NB, b = idx % NB;
        mbuf[n * NB + b] = inM[(size_t)(B0 + b) * IN_F + s*16 + 2*n]
                         + inM[(size_t)(B0 + b) * IN_F + s*16 + 2*n + 1];
    }
    __syncthreads();

    node_lin<MT, true>(val + w*VS, nullptr, mbuf + w*NB, nullptr,
                       W + (size_t)(o0 + s*8 + w)*1024, val + w*VS, mbuf + w*NB, lane);
    node_lin<MT, true>(val + (4+w)*VS, nullptr, mbuf + (4+w)*NB, nullptr,
                       W + (size_t)(o0 + s*8 + 4 + w)*1024, val + (4+w)*VS, mbuf + (4+w)*NB, lane);
    __syncthreads();

    node_lin<MT, false>(val + 2*w*VS, val + (2*w+1)*VS, mbuf + 2*w*NB, mbuf + (2*w+1)*NB,
                        W + (size_t)(o1 + s*4 + w)*1024, val + 2*w*VS, mbuf + 2*w*NB, lane);
    __syncthreads();

    if (w < 2)
        node_lin<MT, false>(val + 4*w*VS, val + (4*w+2)*VS, mbuf + 4*w*NB, mbuf + (4*w+2)*NB,
                            W + (size_t)(o2 + s*2 + w)*1024, val + 4*w*VS, mbuf + 4*w*NB, lane);
    __syncthreads();

    if (w == 0)
        node_lin<MT, false>(val, val + 4*VS, mbuf, mbuf + 4*NB,
                            W + (size_t)(o3 + s)*1024, val, mbuf, lane);
    __syncthreads();

#pragma unroll
    for (int i = 0; i < MT; i++) {
        const int idx = tid + i * 128;
        const int bb = idx >> 3, k4 = idx & 7;
        float4 v = *(const float4*)(val + bb * 36 + 4 * k4);
        *(float4*)(outY + ((size_t)(B0 + bb) * OUT_F + s) * 32 + 4 * k4) = v;
    }
    if (tid < NB) outM[(size_t)(B0 + tid) * OUT_F + s] = mbuf[tid];
}

// ---------------------------------------------------------------------------
// Tail: (Y,m)[8] -> root -> mixture logsumexp. Grid 16 x 128 thr, 32 batches.
// ---------------------------------------------------------------------------
__global__ void __launch_bounds__(128, 4)
pc_tail(const float* __restrict__ inY, const float* __restrict__ inM,
        const float* __restrict__ W, const float* __restrict__ mlw,
        float* __restrict__ outp) {
    constexpr int MT = 2, VS = 1152, NB = 32;
    extern __shared__ float sm[];
    float* val  = sm;             // 4 slots
    float* mbuf = sm + 4 * VS;    // 4 x 32
    float* lw   = mbuf + 4 * NB;  // 32
    const int B0 = blockIdx.x * NB;
    const int tid = threadIdx.x, w = tid >> 5, lane = tid & 31;

    stage_pairs<8, MT, 1, true>(inY + (size_t)B0 * 8 * 32, val, w, lane);
    {
        const int n = tid >> 5, b = tid & 31;
        mbuf[n * NB + b] = inM[(size_t)(B0 + b) * 8 + 2*n]
                         + inM[(size_t)(B0 + b) * 8 + 2*n + 1];
    }
    if (tid < 32) lw[tid] = mlw[tid];
    __syncthreads();

    node_lin<MT, true>(val + w*VS, nullptr, mbuf + w*NB, nullptr,
                       W + (size_t)(2040 + w)*1024, val + w*VS, mbuf + w*NB, lane);
    __syncthreads();

    if (w < 2)
        node_lin<MT, false>(val + 2*w*VS, val + (2*w+1)*VS, mbuf + 2*w*NB, mbuf + (2*w+1)*NB,
                            W + (size_t)(2044 + w)*1024, val + 2*w*VS, mbuf + 2*w*NB, lane);
    __syncthreads();

    if (w == 0)
        node_lin<MT, false>(val, val + 2*VS, mbuf, mbuf + 2*NB,
                            W + (size_t)2046*1024, val, mbuf, lane);
    __syncthreads();

    if (tid < 32) {
        const int b = tid;
        float m1 = lw[0];
        for (int k = 1; k < 32; k++) m1 = fmaxf(m1, lw[k]);
        float s1 = 0.f;
        for (int k = 0; k < 32; k++) s1 += ex2f((lw[k] - m1) * L2E);
        const float lse = fmaf(lg2f(s1), LN2, m1);
        const float mr = mbuf[b];

        float t[32];
        float m2 = -1e30f;
        for (int k = 0; k < 32; k++) {
            t[k] = 2.f * fmaf(lg2f(val[b * 36 + k]), LN2, mr) + lw[k] - lse;
            m2 = fmaxf(m2, t[k]);
        }
        float s2 = 0.f;
        for (int k = 0; k < 32; k++) s2 += ex2f((t[k] - m2) * L2E);
        outp[B0 + b] = fmaf(lg2f(s2), LN2, m2);
    }
}

// ---------------------------------------------------------------------------
// Launch. Inputs: x f32[512,2048,32], weights f32[2047,32,32],
// fold_idx i32 (trivial (2f,2f+1) pairing -> computed), mix_logw f32[32].
// Output: f32[512].
// ---------------------------------------------------------------------------
extern "C" void kernel_launch(void* const* d_in, const int* in_sizes, int n_in,
                              void* d_out, int out_size) {
    const float* x   = (const float*)d_in[0];
    const float* W   = (const float*)d_in[1];
    const float* mlw = (const float*)d_in[3];
    float* out = (float*)d_out;

    float *y1, *m1, *y2, *m2;
    cudaGetSymbolAddress((void**)&y1, g_Y1);
    cudaGetSymbolAddress((void**)&m1, g_m1);
    cudaGetSymbolAddress((void**)&y2, g_Y2);
    cudaGetSymbolAddress((void**)&m2, g_m2);

    const int smem_k  = (8 * 1152 + 8 * 32) * sizeof(float);           // 37888 B
    const int smem_t  = (4 * 1152 + 4 * 32 + 32) * sizeof(float);      // 19072 B

    pc_k1<2048, 2><<<dim3(128, 16), 128, smem_k>>>(x, W, y1, m1);
    pc_k2<2>      <<<dim3(8, 16),   128, smem_k>>>(y1, m1, W, y2, m2);
    pc_tail       <<<16,            128, smem_t>>>(y2, m2, W, mlw, out);
}

// round 12
// speedup vs baseline: 1.6068x; 1.0385x over previous
#include <cuda_runtime.h>
#include <cstdint>

#define L2E 1.4426950408889634f
#define LN2 0.6931471805599453f

// Inter-kernel (Y, m) scratch + permuted weights (static device mem: allowed)
__device__ float g_Y1[(size_t)512 * 128 * 32];   // 8 MB
__device__ float g_m1[(size_t)512 * 128];
__device__ float g_Y2[(size_t)512 * 8 * 32];
__device__ float g_m2[(size_t)512 * 8];
__device__ float g_Wp[(size_t)2047 * 1024];      // 8 MB, fragment-ordered W

// ---------------------------------------------------------------------------
__device__ __forceinline__ float ex2f(float x) {
    float r; asm("ex2.approx.f32 %0, %1;" : "=f"(r) : "f"(x)); return r;
}
__device__ __forceinline__ float lg2f(float x) {
    float r; asm("lg2.approx.f32 %0, %1;" : "=f"(r) : "f"(x)); return r;
}
__device__ __forceinline__ float rcpf(float x) {
    float r; asm("rcp.approx.f32 %0, %1;" : "=f"(r) : "f"(x)); return r;
}
// m16n8k8 tf32 mma, D += A*B (A passed as f32, truncated by HW)
__device__ __forceinline__ void mma_tf32(float c[4], const float a[4], const uint32_t b[2]) {
    asm("mma.sync.aligned.m16n8k8.row.col.f32.tf32.tf32.f32 "
        "{%0,%1,%2,%3}, {%4,%5,%6,%7}, {%8,%9}, {%0,%1,%2,%3};"
        : "+f"(c[0]), "+f"(c[1]), "+f"(c[2]), "+f"(c[3])
        : "r"(__float_as_uint(a[0])), "r"(__float_as_uint(a[1])),
          "r"(__float_as_uint(a[2])), "r"(__float_as_uint(a[3])),
          "r"(b[0]), "r"(b[1]));
}

// ---------------------------------------------------------------------------
// W permute: Wp[m][((nt*4+kt)*2+v)*32 + lane] = W[m][(8kt+4v+tg)*32 + 8nt+g]
// where lane = 4g+tg. Makes every B-fragment load a 128B coalesced warp LDG.
// ---------------------------------------------------------------------------
__global__ void pc_permW(const float* __restrict__ W, float* __restrict__ Wp) {
    const size_t idx = (size_t)blockIdx.x * 256 + threadIdx.x;
    const int m = (int)(idx >> 10), t = (int)(idx & 1023);
    const int l = t & 31, q = t >> 5;
    const int v = q & 1, kt = (q >> 1) & 3, nt = q >> 3;
    const int g = l >> 2, tg = l & 3;
    Wp[idx] = W[(size_t)m * 1024 + (8 * kt + 4 * v + tg) * 32 + 8 * nt + g];
}

// Fragment load from permuted W: b[kt][v] for this nt, this lane.
#define LOAD_BFRAG(b, wp, nt, lane)                                          \
    _Pragma("unroll")                                                        \
    for (int kt = 0; kt < 4; kt++) {                                         \
        b[kt][0] = __float_as_uint((wp)[(((nt) * 4 + kt) * 2 + 0) * 32 + (lane)]); \
        b[kt][1] = __float_as_uint((wp)[(((nt) * 4 + kt) * 2 + 1) * 32 + (lane)]); \
    }

// Value slots (smem): row-major [b*36 + k], stride 36 -> conflict-free LDS.

// ---------------------------------------------------------------------------
// Leaf node (log-domain input p in slot): e=exp2((p-m)*L2E), Y'=e@W, m'=max.
// ---------------------------------------------------------------------------
template <int MT>
__device__ __forceinline__ void node_leaf(const float* pa, const float* __restrict__ wp,
                                          float* po, float* mo, int lane) {
    const int g = lane >> 2, tg = lane & 3;
    float a[MT][4][4];
#pragma unroll
    for (int mt = 0; mt < MT; mt++)
#pragma unroll
        for (int kt = 0; kt < 4; kt++)
#pragma unroll
            for (int r = 0; r < 4; r++)
                a[mt][kt][r] = pa[(16*mt + 8*(r&1) + g) * 36 + 8*kt + 4*(r>>1) + tg];

    float mx[MT][2];
#pragma unroll
    for (int mt = 0; mt < MT; mt++)
#pragma unroll
        for (int u = 0; u < 2; u++) {
            float m = fmaxf(a[mt][0][u], a[mt][0][u+2]);
#pragma unroll
            for (int kt = 1; kt < 4; kt++)
                m = fmaxf(m, fmaxf(a[mt][kt][u], a[mt][kt][u+2]));
            m = fmaxf(m, __shfl_xor_sync(0xffffffffu, m, 1));
            m = fmaxf(m, __shfl_xor_sync(0xffffffffu, m, 2));
            mx[mt][u] = m;
        }
#pragma unroll
    for (int mt = 0; mt < MT; mt++)
#pragma unroll
        for (int kt = 0; kt < 4; kt++)
#pragma unroll
            for (int r = 0; r < 4; r++)
                a[mt][kt][r] = ex2f(fmaf(a[mt][kt][r], L2E, -mx[mt][r&1] * L2E));

#pragma unroll
    for (int nt = 0; nt < 4; nt++) {
        uint32_t b[4][2];
        LOAD_BFRAG(b, wp, nt, lane);
#pragma unroll
        for (int mt = 0; mt < MT; mt++) {
            float c[4] = {0.f, 0.f, 0.f, 0.f};
#pragma unroll
            for (int kt = 0; kt < 4; kt++) mma_tf32(c, a[mt][kt], b[kt]);
#pragma unroll
            for (int u = 0; u < 2; u++)
                *(float2*)(po + (16*mt + 8*u + g) * 36 + 8*nt + 2*tg) =
                    make_float2(c[2*u], c[2*u+1]);
        }
    }
#pragma unroll
    for (int mt = 0; mt < MT; mt++)
#pragma unroll
        for (int u = 0; u < 2; u++)
            if (tg == 0) mo[16*mt + 8*u + g] = mx[mt][u];
}

// ---------------------------------------------------------------------------
// Linear node: e = (Yl*Yr)/max, Y'=e@W, m' = ml+mr+ln(max).
// PRE: slot already holds the product and mbuf the summed m.
// ---------------------------------------------------------------------------
template <int MT, bool PRE>
__device__ __forceinline__ void node_lin(const float* pa, const float* pb,
                                         const float* ma, const float* mb,
                                         const float* __restrict__ wp,
                                         float* po, float* mo, int lane) {
    const int g = lane >> 2, tg = lane & 3;
    float a[MT][4][4];
#pragma unroll
    for (int mt = 0; mt < MT; mt++)
#pragma unroll
        for (int kt = 0; kt < 4; kt++)
#pragma unroll
            for (int r = 0; r < 4; r++) {
                const int off = (16*mt + 8*(r&1) + g) * 36 + 8*kt + 4*(r>>1) + tg;
                float v = pa[off];
                if constexpr (!PRE) v *= pb[off];
                a[mt][kt][r] = v;
            }
    float ms[MT][2];
#pragma unroll
    for (int mt = 0; mt < MT; mt++)
#pragma unroll
        for (int u = 0; u < 2; u++) {
            const int row = 16*mt + 8*u + g;
            float mm = ma[row];
            if constexpr (!PRE) mm += mb[row];
            ms[mt][u] = mm;
        }
    float Mx[MT][2], rv[MT][2];
#pragma unroll
    for (int mt = 0; mt < MT; mt++)
#pragma unroll
        for (int u = 0; u < 2; u++) {
            float m = fmaxf(a[mt][0][u], a[mt][0][u+2]);
#pragma unroll
            for (int kt = 1; kt < 4; kt++)
                m = fmaxf(m, fmaxf(a[mt][kt][u], a[mt][kt][u+2]));
            m = fmaxf(m, __shfl_xor_sync(0xffffffffu, m, 1));
            m = fmaxf(m, __shfl_xor_sync(0xffffffffu, m, 2));
            Mx[mt][u] = m;
            rv[mt][u] = rcpf(m);
        }
#pragma unroll
    for (int mt = 0; mt < MT; mt++)
#pragma unroll
        for (int kt = 0; kt < 4; kt++)
#pragma unroll
            for (int r = 0; r < 4; r++)
                a[mt][kt][r] *= rv[mt][r&1];

#pragma unroll
    for (int nt = 0; nt < 4; nt++) {
        uint32_t b[4][2];
        LOAD_BFRAG(b, wp, nt, lane);
#pragma unroll
        for (int mt = 0; mt < MT; mt++) {
            float c[4] = {0.f, 0.f, 0.f, 0.f};
#pragma unroll
            for (int kt = 0; kt < 4; kt++) mma_tf32(c, a[mt][kt], b[kt]);
#pragma unroll
            for (int u = 0; u < 2; u++)
                *(float2*)(po + (16*mt + 8*u + g) * 36 + 8*nt + 2*tg) =
                    make_float2(c[2*u], c[2*u+1]);
        }
    }
#pragma unroll
    for (int mt = 0; mt < MT; mt++)
#pragma unroll
        for (int u = 0; u < 2; u++)
            if (tg == 0)
                mo[16*mt + 8*u + g] = fmaf(lg2f(Mx[mt][u]), LN2, ms[mt][u]);
}

// ---------------------------------------------------------------------------
// Stage sibling pairs into slots: slot n = child(2n) (+ or *) child(2n+1).
// ---------------------------------------------------------------------------
template <int IN_F, int MT, int NS, bool MULT>
__device__ __forceinline__ void stage_pairs(const float* __restrict__ src,
                                            float* val, int w, int lane) {
    constexpr int VS = MT * 16 * 36;
    const int k4 = lane & 7, bo = lane >> 3;
#pragma unroll
    for (int ns = 0; ns < NS; ns++) {
        const int n = NS * w + ns;
        float* slot = val + n * VS;
        const float4* xA = (const float4*)(src + (size_t)(2 * n) * 32);
        const float4* xB = xA + 8;
#pragma unroll
        for (int i = 0; i < MT * 4; i++) {
            const int bb = i * 4 + bo;
            const size_t roff = (size_t)bb * IN_F * 8;
            float4 va = xA[roff + k4], vb = xB[roff + k4];
            float4 p;
            if (MULT) p = make_float4(va.x*vb.x, va.y*vb.y, va.z*vb.z, va.w*vb.w);
            else      p = make_float4(va.x+vb.x, va.y+vb.y, va.z+vb.z, va.w+vb.w);
            *(float4*)(slot + bb * 36 + 4 * k4) = p;
        }
    }
}

// ---------------------------------------------------------------------------
// K1: x (log) -> 16-leaf subtree root (Y, m). Grid (IN_F/16, 512/NB), 4 warps.
// ---------------------------------------------------------------------------
template <int IN_F, int MT>
__global__ void __launch_bounds__(128, 4)
pc_k1(const float* __restrict__ in, const float* __restrict__ Wp,
      float* __restrict__ outY, float* __restrict__ outM) {
    constexpr int VS = MT * 16 * 36, NB = MT * 16, OUT_F = IN_F / 16;
    extern __shared__ float sm[];
    float* val  = sm;
    float* mbuf = sm + 8 * VS;
    const int s = blockIdx.x, B0 = blockIdx.y * NB;
    const int tid = threadIdx.x, w = tid >> 5, lane = tid & 31;
    const int o0 = 2048 - IN_F, o1 = o0 + IN_F/2, o2 = o1 + IN_F/4, o3 = o2 + IN_F/8;

    stage_pairs<IN_F, MT, 2, false>(in + ((size_t)B0 * IN_F + s * 16) * 32, val, w, lane);
    __syncthreads();

    node_leaf<MT>(val + w*VS, Wp + (size_t)(o0 + s*8 + w)*1024,
                  val + w*VS, mbuf + w*NB, lane);
    node_leaf<MT>(val + (4+w)*VS, Wp + (size_t)(o0 + s*8 + 4 + w)*1024,
                  val + (4+w)*VS, mbuf + (4+w)*NB, lane);
    __syncthreads();

    node_lin<MT, false>(val + 2*w*VS, val + (2*w+1)*VS, mbuf + 2*w*NB, mbuf + (2*w+1)*NB,
                        Wp + (size_t)(o1 + s*4 + w)*1024, val + 2*w*VS, mbuf + 2*w*NB, lane);
    __syncthreads();

    if (w < 2)
        node_lin<MT, false>(val + 4*w*VS, val + (4*w+2)*VS, mbuf + 4*w*NB, mbuf + (4*w+2)*NB,
                            Wp + (size_t)(o2 + s*2 + w)*1024, val + 4*w*VS, mbuf + 4*w*NB, lane);
    __syncthreads();

    if (w == 0)
        node_lin<MT, false>(val, val + 4*VS, mbuf, mbuf + 4*NB,
                            Wp + (size_t)(o3 + s)*1024, val, mbuf, lane);
    __syncthreads();

#pragma unroll
    for (int i = 0; i < MT; i++) {
        const int idx = tid + i * 128;
        const int bb = idx >> 3, k4 = idx & 7;
        float4 v = *(const float4*)(val + bb * 36 + 4 * k4);
        *(float4*)(outY + ((size_t)(B0 + bb) * OUT_F + s) * 32 + 4 * k4) = v;
    }
    if (tid < NB) outM[(size_t)(B0 + tid) * OUT_F + s] = mbuf[tid];
}

// ---------------------------------------------------------------------------
// K2: (Y,m)[128] -> (Y,m)[8]. All-linear. Grid (8, 512/NB).
// ---------------------------------------------------------------------------
template <int MT>
__global__ void __launch_bounds__(128, 4)
pc_k2(const float* __restrict__ inY, const float* __restrict__ inM,
      const float* __restrict__ Wp,
      float* __restrict__ outY, float* __restrict__ outM) {
    constexpr int IN_F = 128, VS = MT * 16 * 36, NB = MT * 16, OUT_F = 8;
    extern __shared__ float sm[];
    float* val  = sm;
    float* mbuf = sm + 8 * VS;
    const int s = blockIdx.x, B0 = blockIdx.y * NB;
    const int tid = threadIdx.x, w = tid >> 5, lane = tid & 31;
    const int o0 = 1920, o1 = 1984, o2 = 2016, o3 = 2032;

    stage_pairs<IN_F, MT, 2, true>(inY + ((size_t)B0 * IN_F + s * 16) * 32, val, w, lane);
#pragma unroll
    for (int t = 0; t < (8 * NB) / 128; t++) {
        const int idx = tid + t * 128;
        const int n = idx / NB, b = idx % NB;
        mbuf[n * NB + b] = inM[(size_t)(B0 + b) * IN_F + s*16 + 2*n]
                         + inM[(size_t)(B0 + b) * IN_F + s*16 + 2*n + 1];
    }
    __syncthreads();

    node_lin<MT, true>(val + w*VS, nullptr, mbuf + w*NB, nullptr,
                       Wp + (size_t)(o0 + s*8 + w)*1024, val + w*VS, mbuf + w*NB, lane);
    node_lin<MT, true>(val + (4+w)*VS, nullptr, mbuf + (4+w)*NB, nullptr,
                       Wp + (size_t)(o0 + s*8 + 4 + w)*1024, val + (4+w)*VS, mbuf + (4+w)*NB, lane);
    __syncthreads();

    node_lin<MT, false>(val + 2*w*VS, val + (2*w+1)*VS, mbuf + 2*w*NB, mbuf + (2*w+1)*NB,
                        Wp + (size_t)(o1 + s*4 + w)*1024, val + 2*w*VS, mbuf + 2*w*NB, lane);
    __syncthreads();

    if (w < 2)
        node_lin<MT, false>(val + 4*w*VS, val + (4*w+2)*VS, mbuf + 4*w*NB, mbuf + (4*w+2)*NB,
                            Wp + (size_t)(o2 + s*2 + w)*1024, val + 4*w*VS, mbuf + 4*w*NB, lane);
    __syncthreads();

    if (w == 0)
        node_lin<MT, false>(val, val + 4*VS, mbuf, mbuf + 4*NB,
                            Wp + (size_t)(o3 + s)*1024, val, mbuf, lane);
    __syncthreads();

#pragma unroll
    for (int i = 0; i < MT; i++) {
        const int idx = tid + i * 128;
        const int bb = idx >> 3, k4 = idx & 7;
        float4 v = *(const float4*)(val + bb * 36 + 4 * k4);
        *(float4*)(outY + ((size_t)(B0 + bb) * OUT_F + s) * 32 + 4 * k4) = v;
    }
    if (tid < NB) outM[(size_t)(B0 + tid) * OUT_F + s] = mbuf[tid];
}

// ---------------------------------------------------------------------------
// Tail: (Y,m)[8] -> root -> mixture logsumexp. Grid 16 x 128 thr, 32 batches.
// ---------------------------------------------------------------------------
__global__ void __launch_bounds__(128, 4)
pc_tail(const float* __restrict__ inY, const float* __restrict__ inM,
        const float* __restrict__ Wp, const float* __restrict__ mlw,
        float* __restrict__ outp) {
    constexpr int MT = 2, VS = 1152, NB = 32;
    extern __shared__ float sm[];
    float* val  = sm;             // 4 slots
    float* mbuf = sm + 4 * VS;    // 4 x 32
    float* lw   = mbuf + 4 * NB;  // 32
    const int B0 = blockIdx.x * NB;
    const int tid = threadIdx.x, w = tid >> 5, lane = tid & 31;

    stage_pairs<8, MT, 1, true>(inY + (size_t)B0 * 8 * 32, val, w, lane);
    {
        const int n = tid >> 5, b = tid & 31;
        mbuf[n * NB + b] = inM[(size_t)(B0 + b) * 8 + 2*n]
                         + inM[(size_t)(B0 + b) * 8 + 2*n + 1];
    }
    if (tid < 32) lw[tid] = mlw[tid];
    __syncthreads();

    node_lin<MT, true>(val + w*VS, nullptr, mbuf + w*NB, nullptr,
                       Wp + (size_t)(2040 + w)*1024, val + w*VS, mbuf + w*NB, lane);
    __syncthreads();

    if (w < 2)
        node_lin<MT, false>(val + 2*w*VS, val + (2*w+1)*VS, mbuf + 2*w*NB, mbuf + (2*w+1)*NB,
                            Wp + (size_t)(2044 + w)*1024, val + 2*w*VS, mbuf + 2*w*NB, lane);
    __syncthreads();

    if (w == 0)
        node_lin<MT, false>(val, val + 2*VS, mbuf, mbuf + 2*NB,
                            Wp + (size_t)2046*1024, val, mbuf, lane);
    __syncthreads();

    if (tid < 32) {
        const int b = tid;
        float m1 = lw[0];
        for (int k = 1; k < 32; k++) m1 = fmaxf(m1, lw[k]);
        float s1 = 0.f;
        for (int k = 0; k < 32; k++) s1 += ex2f((lw[k] - m1) * L2E);
        const float lse = fmaf(lg2f(s1), LN2, m1);
        const float mr = mbuf[b];

        float t[32];
        float m2 = -1e30f;
        for (int k = 0; k < 32; k++) {
            t[k] = 2.f * fmaf(lg2f(val[b * 36 + k]), LN2, mr) + lw[k] - lse;
            m2 = fmaxf(m2, t[k]);
        }
        float s2 = 0.f;
        for (int k = 0; k < 32; k++) s2 += ex2f((t[k] - m2) * L2E);
        outp[B0 + b] = fmaf(lg2f(s2), LN2, m2);
    }
}

// ---------------------------------------------------------------------------
// Launch. Inputs: x f32[512,2048,32], weights f32[2047,32,32],
// fold_idx i32 (trivial (2f,2f+1) pairing -> computed), mix_logw f32[32].
// Output: f32[512].
// ---------------------------------------------------------------------------
extern "C" void kernel_launch(void* const* d_in, const int* in_sizes, int n_in,
                              void* d_out, int out_size) {
    const float* x   = (const float*)d_in[0];
    const float* W   = (const float*)d_in[1];
    const float* mlw = (const float*)d_in[3];
    float* out = (float*)d_out;

    float *y1, *m1, *y2, *m2, *wp;
    cudaGetSymbolAddress((void**)&y1, g_Y1);
    cudaGetSymbolAddress((void**)&m1, g_m1);
    cudaGetSymbolAddress((void**)&y2, g_Y2);
    cudaGetSymbolAddress((void**)&m2, g_m2);
    cudaGetSymbolAddress((void**)&wp, g_Wp);

    const int smem_k  = (8 * 1152 + 8 * 32) * sizeof(float);           // 37888 B
    const int smem_t  = (4 * 1152 + 4 * 32 + 32) * sizeof(float);      // 19072 B

    pc_permW      <<<8188,          256>>>(W, wp);
    pc_k1<2048, 2><<<dim3(128, 16), 128, smem_k>>>(x, wp, y1, m1);
    pc_k2<2>      <<<dim3(8, 16),   128, smem_k>>>(y1, m1, wp, y2, m2);
    pc_tail       <<<16,            128, smem_t>>>(y2, m2, wp, mlw, out);
}